// round 3
// baseline (speedup 1.0000x reference)
#include <cuda_runtime.h>
#include <math.h>

// ---------------------------------------------------------------------------
// Shapes: B=16, N=128, H=128, M=128.  R = B*N = 2048 rows.
// Pair MLP: 256 -> 256 -> 256 -> 128 (relu each), summed over source j.
// ---------------------------------------------------------------------------

#define R_ 2048

// ------------------------- device scratch (no allocs) ----------------------
__device__ float g_scratch[4200448];
// float offsets into g_scratch
#define OFF_A     0          // [2048][256]
#define OFF_BM    524288     // [2048][256]
#define OFF_MSG   1048576    // [2048][128]
#define OFF_GIN   1310720    // [2048][256]
#define OFF_T1    1835008    // [2048][256]
#define OFF_T2    2359296    // [2048][256]
#define OFF_INP   2883584    // [2048][128]
#define OFF_GATES 3145728    // [2048][512]
#define OFF_SUMH  4194304    // [16][128]
#define OFF_O0    4196352    // [16][256]

// output layout (floats): out[16*64], out_g[2048*128], h_n[2048*128], c_n[2048*128]
#define OUT_OG 1024
#define OUT_H  263168
#define OUT_C  525312

// ---------------------------------------------------------------------------
// Generic tiled linear:  C[M,N] = X[M,K] @ W[N, ldw]^T (+bias) (+=C) (relu)
// X / C may live in g_scratch: pass nullptr + float offset.
// block = 256 threads, 64x64 tile, 4x4 microtile, K must be multiple of 16.
// ---------------------------------------------------------------------------
__global__ __launch_bounds__(256) void linear_kernel(
    const float* __restrict__ Xp, int xo,
    const float* __restrict__ W, const float* __restrict__ bias,
    float* __restrict__ Cp, int co,
    int M, int Nout, int K, int ldw, int do_relu, int do_acc)
{
    const float* X = Xp ? Xp : (const float*)(g_scratch + xo);
    float* C = Cp ? Cp : (g_scratch + co);

    __shared__ float Xs[16 * 64];
    __shared__ float Wsm[16 * 64];

    int t  = threadIdx.x;
    int m0 = blockIdx.y * 64;
    int n0 = blockIdx.x * 64;
    int mt = t >> 4;        // 0..15
    int nt = t & 15;        // 0..15

    float acc[4][4];
#pragma unroll
    for (int r = 0; r < 4; r++)
#pragma unroll
        for (int c = 0; c < 4; c++) acc[r][c] = 0.f;

    int lm = t >> 2;        // 0..63
    int lk = (t & 3) * 4;   // 0,4,8,12

    for (int k0 = 0; k0 < K; k0 += 16) {
        float4 xv = make_float4(0.f, 0.f, 0.f, 0.f);
        float4 wv = make_float4(0.f, 0.f, 0.f, 0.f);
        if (m0 + lm < M) xv = *(const float4*)&X[(size_t)(m0 + lm) * K + k0 + lk];
        if (n0 + lm < Nout) wv = *(const float4*)&W[(size_t)(n0 + lm) * ldw + k0 + lk];
        Xs[(lk + 0) * 64 + lm] = xv.x;
        Xs[(lk + 1) * 64 + lm] = xv.y;
        Xs[(lk + 2) * 64 + lm] = xv.z;
        Xs[(lk + 3) * 64 + lm] = xv.w;
        Wsm[(lk + 0) * 64 + lm] = wv.x;
        Wsm[(lk + 1) * 64 + lm] = wv.y;
        Wsm[(lk + 2) * 64 + lm] = wv.z;
        Wsm[(lk + 3) * 64 + lm] = wv.w;
        __syncthreads();
#pragma unroll
        for (int kk = 0; kk < 16; kk++) {
            float4 a = *(const float4*)&Xs[kk * 64 + mt * 4];
            float4 b = *(const float4*)&Wsm[kk * 64 + nt * 4];
            float av[4] = {a.x, a.y, a.z, a.w};
            float bv[4] = {b.x, b.y, b.z, b.w};
#pragma unroll
            for (int r = 0; r < 4; r++)
#pragma unroll
                for (int c = 0; c < 4; c++) acc[r][c] += av[r] * bv[c];
        }
        __syncthreads();
    }

#pragma unroll
    for (int r = 0; r < 4; r++) {
        int row = m0 + mt * 4 + r;
        if (row >= M) continue;
#pragma unroll
        for (int c = 0; c < 4; c++) {
            int col = n0 + nt * 4 + c;
            if (col >= Nout) continue;
            float v = acc[r][c];
            if (bias) v += bias[col];
            if (do_acc) v += C[(size_t)row * Nout + col];
            if (do_relu) v = fmaxf(v, 0.f);
            C[(size_t)row * Nout + col] = v;
        }
    }
}

// ---------------------------------------------------------------------------
// Fused pair-MLP + source-sum kernel. One CTA per (b,i) row (2048 CTAs).
// H0[j,k] = relu(A[b,j,k] + Bm[b,i,k]); Y1 = relu(H0 @ W1^T + b1);
// msg[m] += sum_j relu(Y1 @ W2^T + b2)[j,m].  j processed in 2 chunks of 64.
// Thread (jt,nt): jt = warp (8 j-rows), nt = lane.
// Layer1 cols: nt*4..+3 and 128+nt*4..+3  (16B lane stride: conflict-free).
// ---------------------------------------------------------------------------
#define PH 264     // SMEM row pitch for H0/Y1 (256 + 8)
#define PW1 260    // Ws pitch, layer1 (256 + 4)
#define PW2 132    // Ws pitch, layer2 (128 + 4)

__global__ __launch_bounds__(256, 1) void msg_kernel(
    const float* __restrict__ W1, const float* __restrict__ b1,
    const float* __restrict__ W2, const float* __restrict__ b2)
{
    const float* gA  = g_scratch + OFF_A;
    const float* gBm = g_scratch + OFF_BM;
    float* gmsg      = g_scratch + OFF_MSG;

    extern __shared__ float sm[];
    float* Bms   = sm;                  // 256
    float* msumS = sm + 256;            // 128
    float* red   = sm + 384;            // 8*128 = 1024
    float* H0s   = sm + 1408;           // 64*PH
    float* Y1s   = H0s + 64 * PH;       // 64*PH
    float* Ws    = Y1s + 64 * PH;       // 16*PW1

    int t   = threadIdx.x;
    int row = blockIdx.x;        // b*128 + i
    int b   = row >> 7;

    Bms[t] = gBm[(size_t)row * 256 + t];
    if (t < 128) msumS[t] = 0.f;
    __syncthreads();

    int jt = t >> 5;     // 0..7   (j-group: 8 rows)
    int nt = t & 31;     // 0..31

    float bb1[8];
#pragma unroll
    for (int c = 0; c < 4; c++) bb1[c] = b1[nt * 4 + c];
#pragma unroll
    for (int c = 0; c < 4; c++) bb1[4 + c] = b1[128 + nt * 4 + c];
    float bb2[4];
#pragma unroll
    for (int c = 0; c < 4; c++) bb2[c] = b2[nt * 4 + c];

    int lm = t >> 2;        // 0..63 (weight-tile loader row)
    int lk = (t & 3) * 4;   // 0,4,8,12

    for (int jc = 0; jc < 128; jc += 64) {
        // ----- H0 = relu(A[j] + Bm) -----
        {
            int jr = t >> 6;            // 0..3
            int kf = (t & 63) * 4;      // 0..252
            float4 bv = *(const float4*)&Bms[kf];
#pragma unroll
            for (int it = 0; it < 16; it++) {
                int j = it * 4 + jr;
                float4 av = *(const float4*)&gA[(size_t)(b * 128 + jc + j) * 256 + kf];
                float4 h;
                h.x = fmaxf(av.x + bv.x, 0.f);
                h.y = fmaxf(av.y + bv.y, 0.f);
                h.z = fmaxf(av.z + bv.z, 0.f);
                h.w = fmaxf(av.w + bv.w, 0.f);
                *(float4*)&H0s[j * PH + kf] = h;
            }
        }
        __syncthreads();

        // ----- layer1: Y1[64,256] = relu(H0 @ W1^T + b1) -----
        {
            float acc[8][8];
#pragma unroll
            for (int r = 0; r < 8; r++)
#pragma unroll
                for (int c = 0; c < 8; c++) acc[r][c] = 0.f;

            for (int k0 = 0; k0 < 256; k0 += 16) {
                // load W1 tile [kk 0..15][n 0..255] transposed into SMEM (pitch PW1)
#pragma unroll
                for (int p = 0; p < 4; p++) {
                    int n = lm + 64 * p;
                    float4 wv = *(const float4*)&W1[(size_t)n * 256 + k0 + lk];
                    Ws[(lk + 0) * PW1 + n] = wv.x;
                    Ws[(lk + 1) * PW1 + n] = wv.y;
                    Ws[(lk + 2) * PW1 + n] = wv.z;
                    Ws[(lk + 3) * PW1 + n] = wv.w;
                }
                __syncthreads();
#pragma unroll
                for (int kk = 0; kk < 16; kk++) {
                    float a[8];
#pragma unroll
                    for (int r = 0; r < 8; r++) a[r] = H0s[(jt * 8 + r) * PH + k0 + kk];
                    float4 w0 = *(const float4*)&Ws[kk * PW1 + nt * 4];
                    float4 w1 = *(const float4*)&Ws[kk * PW1 + 128 + nt * 4];
                    float w[8] = {w0.x, w0.y, w0.z, w0.w, w1.x, w1.y, w1.z, w1.w};
#pragma unroll
                    for (int r = 0; r < 8; r++)
#pragma unroll
                        for (int c = 0; c < 8; c++) acc[r][c] += a[r] * w[c];
                }
                __syncthreads();
            }
            // bias + relu, store Y1s[j][col]; cols nt*4 and 128+nt*4 (conflict-free)
#pragma unroll
            for (int r = 0; r < 8; r++) {
                float4 y0, y1;
                y0.x = fmaxf(acc[r][0] + bb1[0], 0.f);
                y0.y = fmaxf(acc[r][1] + bb1[1], 0.f);
                y0.z = fmaxf(acc[r][2] + bb1[2], 0.f);
                y0.w = fmaxf(acc[r][3] + bb1[3], 0.f);
                y1.x = fmaxf(acc[r][4] + bb1[4], 0.f);
                y1.y = fmaxf(acc[r][5] + bb1[5], 0.f);
                y1.z = fmaxf(acc[r][6] + bb1[6], 0.f);
                y1.w = fmaxf(acc[r][7] + bb1[7], 0.f);
                *(float4*)&Y1s[(jt * 8 + r) * PH + nt * 4] = y0;
                *(float4*)&Y1s[(jt * 8 + r) * PH + 128 + nt * 4] = y1;
            }
        }
        __syncthreads();

        // ----- layer2 + reduce over j -----
        {
            float acc2[8][4];
#pragma unroll
            for (int r = 0; r < 8; r++)
#pragma unroll
                for (int c = 0; c < 4; c++) acc2[r][c] = 0.f;

            for (int k0 = 0; k0 < 256; k0 += 16) {
                // load W2 tile [kk 0..15][m 0..127] (pitch PW2)
                {
                    int m = lm;                    // 0..63
#pragma unroll
                    for (int p = 0; p < 2; p++) {
                        int mm = m + 64 * p;
                        float4 wv = *(const float4*)&W2[(size_t)mm * 256 + k0 + lk];
                        Ws[(lk + 0) * PW2 + mm] = wv.x;
                        Ws[(lk + 1) * PW2 + mm] = wv.y;
                        Ws[(lk + 2) * PW2 + mm] = wv.z;
                        Ws[(lk + 3) * PW2 + mm] = wv.w;
                    }
                }
                __syncthreads();
#pragma unroll
                for (int kk = 0; kk < 16; kk++) {
                    float a[8];
#pragma unroll
                    for (int r = 0; r < 8; r++) a[r] = Y1s[(jt * 8 + r) * PH + k0 + kk];
                    float4 w = *(const float4*)&Ws[kk * PW2 + nt * 4];
#pragma unroll
                    for (int r = 0; r < 8; r++) {
                        acc2[r][0] += a[r] * w.x;
                        acc2[r][1] += a[r] * w.y;
                        acc2[r][2] += a[r] * w.z;
                        acc2[r][3] += a[r] * w.w;
                    }
                }
                __syncthreads();
            }
            // relu+bias, partial sum over this thread's 8 j rows
            float p0 = 0.f, p1 = 0.f, p2 = 0.f, p3 = 0.f;
#pragma unroll
            for (int r = 0; r < 8; r++) {
                p0 += fmaxf(acc2[r][0] + bb2[0], 0.f);
                p1 += fmaxf(acc2[r][1] + bb2[1], 0.f);
                p2 += fmaxf(acc2[r][2] + bb2[2], 0.f);
                p3 += fmaxf(acc2[r][3] + bb2[3], 0.f);
            }
            float4 pv = make_float4(p0, p1, p2, p3);
            *(float4*)&red[jt * 128 + nt * 4] = pv;
        }
        __syncthreads();
        if (t < 128) {
            float s = 0.f;
#pragma unroll
            for (int g = 0; g < 8; g++) s += red[g * 128 + t];
            msumS[t] += s;
        }
        __syncthreads();
    }

    if (t < 128) gmsg[(size_t)row * 128 + t] = msumS[t];
}

// ---------------------------------------------------------------------------
// small helpers
// ---------------------------------------------------------------------------
__global__ void pack_kernel(const float* __restrict__ x)
{
    float* gin = g_scratch + OFF_GIN;
    const float* msg = g_scratch + OFF_MSG;
    int r = blockIdx.x;
    int t = threadIdx.x;
    if (t < 128) gin[r * 256 + t] = x[r * 128 + t];
    else         gin[r * 256 + t] = msg[r * 128 + (t - 128)];
}

__device__ __forceinline__ float sigf(float v) { return 1.f / (1.f + expf(-v)); }

__global__ void lstm_kernel(const float* __restrict__ c0, float* __restrict__ out)
{
    const float* gates = g_scratch + OFF_GATES;
    int idx = blockIdx.x * blockDim.x + threadIdx.x;   // 0 .. 262143
    int r = idx >> 7;
    int m = idx & 127;
    float ig = gates[r * 512 + m];
    float fg = gates[r * 512 + 128 + m];
    float gg = gates[r * 512 + 256 + m];
    float og = gates[r * 512 + 384 + m];
    float c = sigf(fg) * c0[idx] + sigf(ig) * tanhf(gg);
    float h = sigf(og) * tanhf(c);
    out[OUT_OG + idx] = h;
    out[OUT_H + idx] = h;
    out[OUT_C + idx] = c;
}

__global__ void sumhid_kernel(const float* __restrict__ out)
{
    float* sumh = g_scratch + OFF_SUMH;
    int b = blockIdx.x;     // 0..15
    int m = threadIdx.x;    // 0..127
    float s = 0.f;
    for (int n = 0; n < 128; n++)
        s += out[OUT_OG + (b * 128 + n) * 128 + m];
    sumh[b * 128 + m] = s;
}

// ---------------------------------------------------------------------------
// launch
// ---------------------------------------------------------------------------
extern "C" void kernel_launch(void* const* d_in, const int* in_sizes, int n_in,
                              void* d_out, int out_size)
{
    const float* x        = (const float*)d_in[0];
    const float* hidden   = (const float*)d_in[1];
    const float* h0       = (const float*)d_in[2];
    const float* c0       = (const float*)d_in[3];
    const float* f_w0     = (const float*)d_in[4];
    const float* f_b0     = (const float*)d_in[5];
    const float* f_w1     = (const float*)d_in[6];
    const float* f_b1     = (const float*)d_in[7];
    const float* f_w2     = (const float*)d_in[8];
    const float* f_b2     = (const float*)d_in[9];
    const float* g_w0     = (const float*)d_in[10];
    const float* g_b0     = (const float*)d_in[11];
    const float* g_w1     = (const float*)d_in[12];
    const float* g_b1     = (const float*)d_in[13];
    const float* g_w2     = (const float*)d_in[14];
    const float* g_b2     = (const float*)d_in[15];
    const float* lstm_wih = (const float*)d_in[16];
    const float* lstm_whh = (const float*)d_in[17];
    const float* lstm_bih = (const float*)d_in[18];
    const float* lstm_bhh = (const float*)d_in[19];
    const float* o_w0     = (const float*)d_in[20];
    const float* o_b0     = (const float*)d_in[21];
    const float* o_w1     = (const float*)d_in[22];
    const float* o_b1     = (const float*)d_in[23];
    float* out = (float*)d_out;

    const int MSG_SMEM = (256 + 128 + 1024 + 64 * PH * 2 + 16 * PW1) * 4;
    static int smem_set = 0;
    if (!smem_set) {
        cudaFuncSetAttribute(msg_kernel, cudaFuncAttributeMaxDynamicSharedMemorySize, MSG_SMEM);
        smem_set = 1;
    }

    dim3 blk(256);

    // layer0 factorization: A = hidden @ W0[:, :128]^T ; Bm = hidden @ W0[:,128:]^T + b0
    linear_kernel<<<dim3(4, 32), blk>>>(hidden, 0, f_w0,       nullptr, nullptr, OFF_A,  R_, 256, 128, 256, 0, 0);
    linear_kernel<<<dim3(4, 32), blk>>>(hidden, 0, f_w0 + 128, f_b0,    nullptr, OFF_BM, R_, 256, 128, 256, 0, 0);

    // fused pair-MLP + source sum
    msg_kernel<<<R_, blk, MSG_SMEM>>>(f_w1, f_b1, f_w2, f_b2);

    // g-MLP
    pack_kernel<<<R_, blk>>>(x);
    linear_kernel<<<dim3(4, 32), blk>>>(nullptr, OFF_GIN, g_w0, g_b0, nullptr, OFF_T1,  R_, 256, 256, 256, 1, 0);
    linear_kernel<<<dim3(4, 32), blk>>>(nullptr, OFF_T1,  g_w1, g_b1, nullptr, OFF_T2,  R_, 256, 256, 256, 1, 0);
    linear_kernel<<<dim3(2, 32), blk>>>(nullptr, OFF_T2,  g_w2, g_b2, nullptr, OFF_INP, R_, 128, 256, 256, 1, 0);

    // LSTM gates = inp @ wih^T + bih + h0 @ whh^T + bhh
    linear_kernel<<<dim3(8, 32), blk>>>(nullptr, OFF_INP, lstm_wih, lstm_bih, nullptr, OFF_GATES, R_, 512, 128, 128, 0, 0);
    linear_kernel<<<dim3(8, 32), blk>>>(h0, 0,            lstm_whh, lstm_bhh, nullptr, OFF_GATES, R_, 512, 128, 128, 0, 1);
    lstm_kernel<<<1024, 256>>>(c0, out);

    // output head
    sumhid_kernel<<<16, 128>>>(out);
    linear_kernel<<<dim3(4, 1), blk>>>(nullptr, OFF_SUMH, o_w0, o_b0, nullptr, OFF_O0, 16, 256, 128, 128, 1, 0);
    linear_kernel<<<dim3(1, 1), blk>>>(nullptr, OFF_O0,   o_w1, o_b1, out, 0,          16, 64,  256, 256, 1, 0);
}

// round 4
// speedup vs baseline: 1.0355x; 1.0355x over previous
#include <cuda_runtime.h>
#include <math.h>

// ---------------------------------------------------------------------------
// Shapes: B=16, N=128, H=128, M=128.  R = B*N = 2048 rows.
// Pair MLP: 256 -> 256 -> 256 -> 128 (relu each), summed over source j.
// f32x2 packed-FMA version: accumulators packed over column pairs.
// ---------------------------------------------------------------------------

#define R_ 2048

typedef unsigned long long ull;

// packed f32x2 helpers (Blackwell sm_100+)
#define PACK2(d, lo, hi) asm("mov.b64 %0, {%1, %2};" : "=l"(d) : "f"(lo), "f"(hi))
#define BCAST2(d, v)     asm("mov.b64 %0, {%1, %1};" : "=l"(d) : "f"(v))
#define FMA2(d, a, b)    asm("fma.rn.f32x2 %0, %1, %2, %0;" : "+l"(d) : "l"(a), "l"(b))
#define UNPK2(lo, hi, s) asm("mov.b64 {%0, %1}, %2;" : "=f"(lo), "=f"(hi) : "l"(s))

// ------------------------- device scratch (no allocs) ----------------------
__device__ float g_scratch[4200448];
// float offsets into g_scratch
#define OFF_A     0          // [2048][256]
#define OFF_BM    524288     // [2048][256]
#define OFF_MSG   1048576    // [2048][128]
#define OFF_GIN   1310720    // [2048][256]
#define OFF_T1    1835008    // [2048][256]
#define OFF_T2    2359296    // [2048][256]
#define OFF_INP   2883584    // [2048][128]
#define OFF_GATES 3145728    // [2048][512]
#define OFF_SUMH  4194304    // [16][128]
#define OFF_O0    4196352    // [16][256]

// output layout (floats): out[16*64], out_g[2048*128], h_n[2048*128], c_n[2048*128]
#define OUT_OG 1024
#define OUT_H  263168
#define OUT_C  525312

// ---------------------------------------------------------------------------
// Generic tiled linear:  C[M,N] = X[M,K] @ W[N, ldw]^T (+bias) (+=C) (relu)
// X / C may live in g_scratch: pass nullptr + float offset.
// block = 256 threads, 64x64 tile, 4x4 microtile (packed 4x2), K mult of 16.
// ---------------------------------------------------------------------------
__global__ __launch_bounds__(256) void linear_kernel(
    const float* __restrict__ Xp, int xo,
    const float* __restrict__ W, const float* __restrict__ bias,
    float* __restrict__ Cp, int co,
    int M, int Nout, int K, int ldw, int do_relu, int do_acc)
{
    const float* X = Xp ? Xp : (const float*)(g_scratch + xo);
    float* C = Cp ? Cp : (g_scratch + co);

    __shared__ float Xs[16 * 64];
    __shared__ float Wsm[16 * 64];

    int t  = threadIdx.x;
    int m0 = blockIdx.y * 64;
    int n0 = blockIdx.x * 64;
    int mt = t >> 4;        // 0..15
    int nt = t & 15;        // 0..15

    ull acc[4][2];
#pragma unroll
    for (int r = 0; r < 4; r++)
#pragma unroll
        for (int c = 0; c < 2; c++) acc[r][c] = 0ull;

    int lm = t >> 2;        // 0..63
    int lk = (t & 3) * 4;   // 0,4,8,12

    for (int k0 = 0; k0 < K; k0 += 16) {
        float4 xv = make_float4(0.f, 0.f, 0.f, 0.f);
        float4 wv = make_float4(0.f, 0.f, 0.f, 0.f);
        if (m0 + lm < M) xv = *(const float4*)&X[(size_t)(m0 + lm) * K + k0 + lk];
        if (n0 + lm < Nout) wv = *(const float4*)&W[(size_t)(n0 + lm) * ldw + k0 + lk];
        Xs[(lk + 0) * 64 + lm] = xv.x;
        Xs[(lk + 1) * 64 + lm] = xv.y;
        Xs[(lk + 2) * 64 + lm] = xv.z;
        Xs[(lk + 3) * 64 + lm] = xv.w;
        Wsm[(lk + 0) * 64 + lm] = wv.x;
        Wsm[(lk + 1) * 64 + lm] = wv.y;
        Wsm[(lk + 2) * 64 + lm] = wv.z;
        Wsm[(lk + 3) * 64 + lm] = wv.w;
        __syncthreads();
#pragma unroll
        for (int kk = 0; kk < 16; kk++) {
            float4 a = *(const float4*)&Xs[kk * 64 + mt * 4];
            float4 b = *(const float4*)&Wsm[kk * 64 + nt * 4];
            ull ap[4];
            BCAST2(ap[0], a.x); BCAST2(ap[1], a.y);
            BCAST2(ap[2], a.z); BCAST2(ap[3], a.w);
            ull bp[2];
            PACK2(bp[0], b.x, b.y);
            PACK2(bp[1], b.z, b.w);
#pragma unroll
            for (int r = 0; r < 4; r++) {
                FMA2(acc[r][0], ap[r], bp[0]);
                FMA2(acc[r][1], ap[r], bp[1]);
            }
        }
        __syncthreads();
    }

#pragma unroll
    for (int r = 0; r < 4; r++) {
        int row = m0 + mt * 4 + r;
        if (row >= M) continue;
        float av[4];
        UNPK2(av[0], av[1], acc[r][0]);
        UNPK2(av[2], av[3], acc[r][1]);
#pragma unroll
        for (int c = 0; c < 4; c++) {
            int col = n0 + nt * 4 + c;
            if (col >= Nout) continue;
            float v = av[c];
            if (bias) v += bias[col];
            if (do_acc) v += C[(size_t)row * Nout + col];
            if (do_relu) v = fmaxf(v, 0.f);
            C[(size_t)row * Nout + col] = v;
        }
    }
}

// ---------------------------------------------------------------------------
// Fused pair-MLP + source-sum kernel. One CTA per (b,i) row (2048 CTAs).
// H0[j,k] = relu(A[b,j,k] + Bm[b,i,k]); Y1 = relu(H0 @ W1^T + b1);
// msg[m] += sum_j relu(Y1 @ W2^T + b2)[j,m].  j processed in 2 chunks of 64.
// Thread (jt,nt): jt = warp (8 j-rows), nt = lane.
// Layer1 cols: nt*4..+3 and 128+nt*4..+3  (16B lane stride: conflict-free).
// Accumulators packed f32x2 over column pairs.
// ---------------------------------------------------------------------------
#define PH 264     // SMEM row pitch for H0/Y1 (256 + 8)
#define PW1 260    // Ws pitch, layer1 (256 + 4)
#define PW2 132    // Ws pitch, layer2 (128 + 4)

__global__ __launch_bounds__(256, 1) void msg_kernel(
    const float* __restrict__ W1, const float* __restrict__ b1,
    const float* __restrict__ W2, const float* __restrict__ b2)
{
    const float* gA  = g_scratch + OFF_A;
    const float* gBm = g_scratch + OFF_BM;
    float* gmsg      = g_scratch + OFF_MSG;

    extern __shared__ float sm[];
    float* Bms   = sm;                  // 256
    float* msumS = sm + 256;            // 128
    float* red   = sm + 384;            // 8*128 = 1024
    float* H0s   = sm + 1408;           // 64*PH
    float* Y1s   = H0s + 64 * PH;       // 64*PH
    float* Ws    = Y1s + 64 * PH;       // 16*PW1

    int t   = threadIdx.x;
    int row = blockIdx.x;        // b*128 + i
    int b   = row >> 7;

    Bms[t] = gBm[(size_t)row * 256 + t];
    if (t < 128) msumS[t] = 0.f;
    __syncthreads();

    int jt = t >> 5;     // 0..7   (j-group: 8 rows)
    int nt = t & 31;     // 0..31

    float bb1[8];
#pragma unroll
    for (int c = 0; c < 4; c++) bb1[c] = b1[nt * 4 + c];
#pragma unroll
    for (int c = 0; c < 4; c++) bb1[4 + c] = b1[128 + nt * 4 + c];
    float bb2[4];
#pragma unroll
    for (int c = 0; c < 4; c++) bb2[c] = b2[nt * 4 + c];

    int lm = t >> 2;        // 0..63 (weight-tile loader row)
    int lk = (t & 3) * 4;   // 0,4,8,12

    for (int jc = 0; jc < 128; jc += 64) {
        // ----- H0 = relu(A[j] + Bm) -----
        {
            int jr = t >> 6;            // 0..3
            int kf = (t & 63) * 4;      // 0..252
            float4 bv = *(const float4*)&Bms[kf];
#pragma unroll
            for (int it = 0; it < 16; it++) {
                int j = it * 4 + jr;
                float4 av = *(const float4*)&gA[(size_t)(b * 128 + jc + j) * 256 + kf];
                float4 h;
                h.x = fmaxf(av.x + bv.x, 0.f);
                h.y = fmaxf(av.y + bv.y, 0.f);
                h.z = fmaxf(av.z + bv.z, 0.f);
                h.w = fmaxf(av.w + bv.w, 0.f);
                *(float4*)&H0s[j * PH + kf] = h;
            }
        }
        __syncthreads();

        // ----- layer1: Y1[64,256] = relu(H0 @ W1^T + b1) -----
        {
            ull acc[8][4];
#pragma unroll
            for (int r = 0; r < 8; r++)
#pragma unroll
                for (int c = 0; c < 4; c++) acc[r][c] = 0ull;

            for (int k0 = 0; k0 < 256; k0 += 16) {
                // load W1 tile [kk 0..15][n 0..255] transposed into SMEM (pitch PW1)
#pragma unroll
                for (int p = 0; p < 4; p++) {
                    int n = lm + 64 * p;
                    float4 wv = *(const float4*)&W1[(size_t)n * 256 + k0 + lk];
                    Ws[(lk + 0) * PW1 + n] = wv.x;
                    Ws[(lk + 1) * PW1 + n] = wv.y;
                    Ws[(lk + 2) * PW1 + n] = wv.z;
                    Ws[(lk + 3) * PW1 + n] = wv.w;
                }
                __syncthreads();
#pragma unroll
                for (int kk = 0; kk < 16; kk++) {
                    ull ap[8];
#pragma unroll
                    for (int r = 0; r < 8; r++) {
                        float a = H0s[(jt * 8 + r) * PH + k0 + kk];
                        BCAST2(ap[r], a);
                    }
                    float4 w0 = *(const float4*)&Ws[kk * PW1 + nt * 4];
                    float4 w1 = *(const float4*)&Ws[kk * PW1 + 128 + nt * 4];
                    ull wp[4];
                    PACK2(wp[0], w0.x, w0.y);
                    PACK2(wp[1], w0.z, w0.w);
                    PACK2(wp[2], w1.x, w1.y);
                    PACK2(wp[3], w1.z, w1.w);
#pragma unroll
                    for (int r = 0; r < 8; r++) {
                        FMA2(acc[r][0], ap[r], wp[0]);
                        FMA2(acc[r][1], ap[r], wp[1]);
                        FMA2(acc[r][2], ap[r], wp[2]);
                        FMA2(acc[r][3], ap[r], wp[3]);
                    }
                }
                __syncthreads();
            }
            // bias + relu, store Y1s[j][col]; cols nt*4 and 128+nt*4 (conflict-free)
#pragma unroll
            for (int r = 0; r < 8; r++) {
                float a0, a1, a2, a3, a4, a5, a6, a7;
                UNPK2(a0, a1, acc[r][0]);
                UNPK2(a2, a3, acc[r][1]);
                UNPK2(a4, a5, acc[r][2]);
                UNPK2(a6, a7, acc[r][3]);
                float4 y0, y1;
                y0.x = fmaxf(a0 + bb1[0], 0.f);
                y0.y = fmaxf(a1 + bb1[1], 0.f);
                y0.z = fmaxf(a2 + bb1[2], 0.f);
                y0.w = fmaxf(a3 + bb1[3], 0.f);
                y1.x = fmaxf(a4 + bb1[4], 0.f);
                y1.y = fmaxf(a5 + bb1[5], 0.f);
                y1.z = fmaxf(a6 + bb1[6], 0.f);
                y1.w = fmaxf(a7 + bb1[7], 0.f);
                *(float4*)&Y1s[(jt * 8 + r) * PH + nt * 4] = y0;
                *(float4*)&Y1s[(jt * 8 + r) * PH + 128 + nt * 4] = y1;
            }
        }
        __syncthreads();

        // ----- layer2 + reduce over j -----
        {
            ull acc2[8][2];
#pragma unroll
            for (int r = 0; r < 8; r++)
#pragma unroll
                for (int c = 0; c < 2; c++) acc2[r][c] = 0ull;

            for (int k0 = 0; k0 < 256; k0 += 16) {
                // load W2 tile [kk 0..15][m 0..127] (pitch PW2)
                {
                    int m = lm;                    // 0..63
#pragma unroll
                    for (int p = 0; p < 2; p++) {
                        int mm = m + 64 * p;
                        float4 wv = *(const float4*)&W2[(size_t)mm * 256 + k0 + lk];
                        Ws[(lk + 0) * PW2 + mm] = wv.x;
                        Ws[(lk + 1) * PW2 + mm] = wv.y;
                        Ws[(lk + 2) * PW2 + mm] = wv.z;
                        Ws[(lk + 3) * PW2 + mm] = wv.w;
                    }
                }
                __syncthreads();
#pragma unroll
                for (int kk = 0; kk < 16; kk++) {
                    ull ap[8];
#pragma unroll
                    for (int r = 0; r < 8; r++) {
                        float a = Y1s[(jt * 8 + r) * PH + k0 + kk];
                        BCAST2(ap[r], a);
                    }
                    float4 w = *(const float4*)&Ws[kk * PW2 + nt * 4];
                    ull wp[2];
                    PACK2(wp[0], w.x, w.y);
                    PACK2(wp[1], w.z, w.w);
#pragma unroll
                    for (int r = 0; r < 8; r++) {
                        FMA2(acc2[r][0], ap[r], wp[0]);
                        FMA2(acc2[r][1], ap[r], wp[1]);
                    }
                }
                __syncthreads();
            }
            // relu+bias, partial sum over this thread's 8 j rows
            float p0 = 0.f, p1 = 0.f, p2 = 0.f, p3 = 0.f;
#pragma unroll
            for (int r = 0; r < 8; r++) {
                float a0, a1, a2, a3;
                UNPK2(a0, a1, acc2[r][0]);
                UNPK2(a2, a3, acc2[r][1]);
                p0 += fmaxf(a0 + bb2[0], 0.f);
                p1 += fmaxf(a1 + bb2[1], 0.f);
                p2 += fmaxf(a2 + bb2[2], 0.f);
                p3 += fmaxf(a3 + bb2[3], 0.f);
            }
            float4 pv = make_float4(p0, p1, p2, p3);
            *(float4*)&red[jt * 128 + nt * 4] = pv;
        }
        __syncthreads();
        if (t < 128) {
            float s = 0.f;
#pragma unroll
            for (int g = 0; g < 8; g++) s += red[g * 128 + t];
            msumS[t] += s;
        }
        __syncthreads();
    }

    if (t < 128) gmsg[(size_t)row * 128 + t] = msumS[t];
}

// ---------------------------------------------------------------------------
// small helpers
// ---------------------------------------------------------------------------
__global__ void pack_kernel(const float* __restrict__ x)
{
    float* gin = g_scratch + OFF_GIN;
    const float* msg = g_scratch + OFF_MSG;
    int r = blockIdx.x;
    int t = threadIdx.x;
    if (t < 128) gin[r * 256 + t] = x[r * 128 + t];
    else         gin[r * 256 + t] = msg[r * 128 + (t - 128)];
}

__device__ __forceinline__ float sigf(float v) { return 1.f / (1.f + expf(-v)); }

__global__ void lstm_kernel(const float* __restrict__ c0, float* __restrict__ out)
{
    const float* gates = g_scratch + OFF_GATES;
    int idx = blockIdx.x * blockDim.x + threadIdx.x;   // 0 .. 262143
    int r = idx >> 7;
    int m = idx & 127;
    float ig = gates[r * 512 + m];
    float fg = gates[r * 512 + 128 + m];
    float gg = gates[r * 512 + 256 + m];
    float og = gates[r * 512 + 384 + m];
    float c = sigf(fg) * c0[idx] + sigf(ig) * tanhf(gg);
    float h = sigf(og) * tanhf(c);
    out[OUT_OG + idx] = h;
    out[OUT_H + idx] = h;
    out[OUT_C + idx] = c;
}

__global__ void sumhid_kernel(const float* __restrict__ out)
{
    float* sumh = g_scratch + OFF_SUMH;
    int b = blockIdx.x;     // 0..15
    int m = threadIdx.x;    // 0..127
    float s = 0.f;
    for (int n = 0; n < 128; n++)
        s += out[OUT_OG + (b * 128 + n) * 128 + m];
    sumh[b * 128 + m] = s;
}

// ---------------------------------------------------------------------------
// launch
// ---------------------------------------------------------------------------
extern "C" void kernel_launch(void* const* d_in, const int* in_sizes, int n_in,
                              void* d_out, int out_size)
{
    const float* x        = (const float*)d_in[0];
    const float* hidden   = (const float*)d_in[1];
    const float* h0       = (const float*)d_in[2];
    const float* c0       = (const float*)d_in[3];
    const float* f_w0     = (const float*)d_in[4];
    const float* f_b0     = (const float*)d_in[5];
    const float* f_w1     = (const float*)d_in[6];
    const float* f_b1     = (const float*)d_in[7];
    const float* f_w2     = (const float*)d_in[8];
    const float* f_b2     = (const float*)d_in[9];
    const float* g_w0     = (const float*)d_in[10];
    const float* g_b0     = (const float*)d_in[11];
    const float* g_w1     = (const float*)d_in[12];
    const float* g_b1     = (const float*)d_in[13];
    const float* g_w2     = (const float*)d_in[14];
    const float* g_b2     = (const float*)d_in[15];
    const float* lstm_wih = (const float*)d_in[16];
    const float* lstm_whh = (const float*)d_in[17];
    const float* lstm_bih = (const float*)d_in[18];
    const float* lstm_bhh = (const float*)d_in[19];
    const float* o_w0     = (const float*)d_in[20];
    const float* o_b0     = (const float*)d_in[21];
    const float* o_w1     = (const float*)d_in[22];
    const float* o_b1     = (const float*)d_in[23];
    float* out = (float*)d_out;

    const int MSG_SMEM = (256 + 128 + 1024 + 64 * PH * 2 + 16 * PW1) * 4;
    static int smem_set = 0;
    if (!smem_set) {
        cudaFuncSetAttribute(msg_kernel, cudaFuncAttributeMaxDynamicSharedMemorySize, MSG_SMEM);
        smem_set = 1;
    }

    dim3 blk(256);

    // layer0 factorization: A = hidden @ W0[:, :128]^T ; Bm = hidden @ W0[:,128:]^T + b0
    linear_kernel<<<dim3(4, 32), blk>>>(hidden, 0, f_w0,       nullptr, nullptr, OFF_A,  R_, 256, 128, 256, 0, 0);
    linear_kernel<<<dim3(4, 32), blk>>>(hidden, 0, f_w0 + 128, f_b0,    nullptr, OFF_BM, R_, 256, 128, 256, 0, 0);

    // fused pair-MLP + source sum
    msg_kernel<<<R_, blk, MSG_SMEM>>>(f_w1, f_b1, f_w2, f_b2);

    // g-MLP
    pack_kernel<<<R_, blk>>>(x);
    linear_kernel<<<dim3(4, 32), blk>>>(nullptr, OFF_GIN, g_w0, g_b0, nullptr, OFF_T1,  R_, 256, 256, 256, 1, 0);
    linear_kernel<<<dim3(4, 32), blk>>>(nullptr, OFF_T1,  g_w1, g_b1, nullptr, OFF_T2,  R_, 256, 256, 256, 1, 0);
    linear_kernel<<<dim3(2, 32), blk>>>(nullptr, OFF_T2,  g_w2, g_b2, nullptr, OFF_INP, R_, 128, 256, 256, 1, 0);

    // LSTM gates = inp @ wih^T + bih + h0 @ whh^T + bhh
    linear_kernel<<<dim3(8, 32), blk>>>(nullptr, OFF_INP, lstm_wih, lstm_bih, nullptr, OFF_GATES, R_, 512, 128, 128, 0, 0);
    linear_kernel<<<dim3(8, 32), blk>>>(h0, 0,            lstm_whh, lstm_bhh, nullptr, OFF_GATES, R_, 512, 128, 128, 0, 1);
    lstm_kernel<<<1024, 256>>>(c0, out);

    // output head
    sumhid_kernel<<<16, 128>>>(out);
    linear_kernel<<<dim3(4, 1), blk>>>(nullptr, OFF_SUMH, o_w0, o_b0, nullptr, OFF_O0, 16, 256, 128, 128, 1, 0);
    linear_kernel<<<dim3(1, 1), blk>>>(nullptr, OFF_O0,   o_w1, o_b1, out, 0,          16, 64,  256, 256, 1, 0);
}

// round 7
// speedup vs baseline: 1.1969x; 1.1558x over previous
#include <cuda_runtime.h>
#include <cuda_bf16.h>
#include <stdint.h>
#include <math.h>

// ---------------------------------------------------------------------------
// Shapes: B=16, N=128, H=128, M=128.  R = B*N = 2048 rows.
// Pair MLP: 256 -> 256 -> 256 -> 128 (relu each), summed over source j.
// Round 7: pair-MLP on mma.sync.m16n8k16 bf16 (sm_80+ path; sm_100 'a'
// features unavailable in this build) with hi/lo split, fp32 accumulate.
// ---------------------------------------------------------------------------

#define R_ 2048

// ------------------------- device scratch (no allocs) ----------------------
__device__ float g_scratch[4298752];
#define OFF_A     0          // [2048][256] fp32
#define OFF_BM    524288     // [2048][256] fp32 (includes f_b0)
#define OFF_MSG   1048576    // [2048][128]
#define OFF_GIN   1310720    // [2048][256]
#define OFF_T1    1835008    // [2048][256]
#define OFF_T2    2359296    // [2048][256]
#define OFF_INP   2883584    // [2048][128]
#define OFF_GATES 3145728    // [2048][512]
#define OFF_SUMH  4194304    // [16][128]
#define OFF_O0    4196352    // [16][256]
#define OFF_W1HI  4200448    // 65536 bf16
#define OFF_W1LO  4233216
#define OFF_W2HI  4265984    // 32768 bf16
#define OFF_W2LO  4282368

// output layout (floats): out[16*64], out_g[2048*128], h_n[2048*128], c_n[2048*128]
#define OUT_OG 1024
#define OUT_H  263168
#define OUT_C  525312

// =========================== mma helpers ====================================
__device__ __forceinline__ uint32_t s2u(const void* p) {
    uint32_t a;
    asm("{ .reg .u64 t; cvta.to.shared.u64 t, %1; cvt.u32.u64 %0, t; }"
        : "=r"(a) : "l"(p));
    return a;
}

#define LDSM4(r, addr) \
    asm volatile("ldmatrix.sync.aligned.m8n8.x4.shared.b16 {%0,%1,%2,%3}, [%4];" \
        : "=r"((r)[0]), "=r"((r)[1]), "=r"((r)[2]), "=r"((r)[3]) : "r"(addr))

#define MMA16816(d, a, b0_, b1_) \
    asm volatile("mma.sync.aligned.m16n8k16.row.col.f32.bf16.bf16.f32 " \
        "{%0,%1,%2,%3}, {%4,%5,%6,%7}, {%8,%9}, {%0,%1,%2,%3};" \
        : "+f"((d)[0]), "+f"((d)[1]), "+f"((d)[2]), "+f"((d)[3]) \
        : "r"((a)[0]), "r"((a)[1]), "r"((a)[2]), "r"((a)[3]), \
          "r"(b0_), "r"(b1_))

__device__ __forceinline__ void split2(float y0, float y1,
                                       uint32_t& hw, uint32_t& lw) {
    __nv_bfloat16 h0 = __float2bfloat16(y0);
    __nv_bfloat16 h1 = __float2bfloat16(y1);
    float l0 = y0 - __bfloat162float(h0);
    float l1 = y1 - __bfloat162float(h1);
    hw = (uint32_t)__bfloat16_as_ushort(h0) |
         ((uint32_t)__bfloat16_as_ushort(h1) << 16);
    lw = (uint32_t)__bfloat16_as_ushort(__float2bfloat16(l0)) |
         ((uint32_t)__bfloat16_as_ushort(__float2bfloat16(l1)) << 16);
}

// ---------------------------------------------------------------------------
// Weight split prep: W1 (256x256) and W2 (128x256) fp32 -> bf16 hi/lo.
// ---------------------------------------------------------------------------
__global__ void wsplit_kernel(const float* __restrict__ W1,
                              const float* __restrict__ W2)
{
    int i = blockIdx.x * blockDim.x + threadIdx.x;
    __nv_bfloat16* w1h = (__nv_bfloat16*)(g_scratch + OFF_W1HI);
    __nv_bfloat16* w1l = (__nv_bfloat16*)(g_scratch + OFF_W1LO);
    __nv_bfloat16* w2h = (__nv_bfloat16*)(g_scratch + OFF_W2HI);
    __nv_bfloat16* w2l = (__nv_bfloat16*)(g_scratch + OFF_W2LO);
    if (i < 65536) {
        float w = W1[i];
        __nv_bfloat16 h = __float2bfloat16(w);
        w1h[i] = h;
        w1l[i] = __float2bfloat16(w - __bfloat162float(h));
    }
    if (i < 32768) {
        float w = W2[i];
        __nv_bfloat16 h = __float2bfloat16(w);
        w2h[i] = h;
        w2l[i] = __float2bfloat16(w - __bfloat162float(h));
    }
}

// ---------------------------------------------------------------------------
// SMEM layout (bytes). Tiles: 128 rows x 64 bf16, pitch 144B (conflict-free).
// ---------------------------------------------------------------------------
#define SM_RED   0        // 8*128 f32 = 4096
#define SM_B1    4096     // 256 f32
#define SM_B2    5120     // 128 f32
#define SM_BM    5632     // 256 f32
#define SM_HHI   6656     // 128*144 = 18432
#define SM_HLO   25088
#define SM_WHI   43520
#define SM_WLO   61952
#define MSG_SMEM 80384
#define TP 144            // tile row pitch bytes

// One K16-step x all 16 n8-tiles x 3 hi/lo passes, into acc[16][4].
__device__ __forceinline__ void gemm_chunk(uint32_t smem_base, int w, int lane,
                                           float (*acc)[4])
{
#pragma unroll
    for (int ks = 0; ks < 4; ks++) {
        uint32_t ah[4], al[4];
        uint32_t arow = (uint32_t)(16 * w + (lane & 15));
        uint32_t akof = (uint32_t)(ks * 16 + ((lane >> 4) << 3));
        uint32_t aaddr = smem_base + SM_HHI + arow * TP + akof * 2;
        LDSM4(ah, aaddr);
        LDSM4(al, aaddr + (SM_HLO - SM_HHI));
#pragma unroll
        for (int nt2 = 0; nt2 < 8; nt2++) {
            uint32_t brow = (uint32_t)(nt2 * 16 + (lane & 7) + ((lane >> 4) << 3));
            uint32_t bkof = (uint32_t)(ks * 16 + (((lane >> 3) & 1) << 3));
            uint32_t baddr = smem_base + SM_WHI + brow * TP + bkof * 2;
            uint32_t bh[4], bl[4];
            LDSM4(bh, baddr);
            LDSM4(bl, baddr + (SM_WLO - SM_WHI));
            MMA16816(acc[nt2 * 2],     ah, bh[0], bh[1]);
            MMA16816(acc[nt2 * 2 + 1], ah, bh[2], bh[3]);
            MMA16816(acc[nt2 * 2],     ah, bl[0], bl[1]);
            MMA16816(acc[nt2 * 2 + 1], ah, bl[2], bl[3]);
            MMA16816(acc[nt2 * 2],     al, bh[0], bh[1]);
            MMA16816(acc[nt2 * 2 + 1], al, bh[2], bh[3]);
        }
    }
}

// ---------------------------------------------------------------------------
// Fused pair-MLP + source-sum. One CTA per (b,i) row, 256 threads, 8 warps.
// Warp w owns output rows 16w..16w+15 (j index). Layer1: N=256 in two
// 128-col halves; layer2 consumes Y1 halves chunk-by-chunk (K-chunks),
// with a persistent 128-col accumulator. All hi/lo bf16 3-pass.
// ---------------------------------------------------------------------------
__global__ __launch_bounds__(256, 1) void msg_kernel(
    const float* __restrict__ b1g, const float* __restrict__ b2g)
{
    extern __shared__ char smc[];
    const uint32_t smem_base = s2u(smc);

    const float* gA  = g_scratch + OFF_A;
    const float* gBm = g_scratch + OFF_BM;
    float* gmsg      = g_scratch + OFF_MSG;
    const __nv_bfloat16* w1h = (const __nv_bfloat16*)(g_scratch + OFF_W1HI);
    const __nv_bfloat16* w1l = (const __nv_bfloat16*)(g_scratch + OFF_W1LO);
    const __nv_bfloat16* w2h = (const __nv_bfloat16*)(g_scratch + OFF_W2HI);
    const __nv_bfloat16* w2l = (const __nv_bfloat16*)(g_scratch + OFF_W2LO);

    float* red = (float*)(smc + SM_RED);
    float* b1s = (float*)(smc + SM_B1);
    float* b2s = (float*)(smc + SM_B2);
    float* Bms = (float*)(smc + SM_BM);

    int t    = threadIdx.x;
    int w    = t >> 5;
    int lane = t & 31;
    int g    = lane >> 2;
    int tg   = lane & 3;
    int row  = blockIdx.x;     // b*128 + i
    int b    = row >> 7;

    b1s[t] = b1g[t];
    if (t < 128) b2s[t] = b2g[t];
    Bms[t] = gBm[(size_t)row * 256 + t];

    float acc2[16][4];
#pragma unroll
    for (int i = 0; i < 16; i++)
#pragma unroll
        for (int c = 0; c < 4; c++) acc2[i][c] = 0.f;

    int lr   = t >> 1;     // loader row 0..127
    int half = t & 1;      // loader col half

    for (int nh = 0; nh < 2; nh++) {
        float acc1[16][4];
#pragma unroll
        for (int i = 0; i < 16; i++)
#pragma unroll
            for (int c = 0; c < 4; c++) acc1[i][c] = 0.f;

        // ---------- Layer 1: acc1 = H0 @ W1[nh half]^T ----------
        for (int kc = 0; kc < 4; kc++) {
            __syncthreads();   // Hbuf/Wbuf free from previous phase
            // build H0 chunk (relu(A+Bm)), split hi/lo into Hbuf
            {
                const float* arow = gA + (size_t)(b * 128 + lr) * 256 + kc * 64 + half * 32;
                const float* bmp  = Bms + kc * 64 + half * 32;
                uint32_t hw[16], lw[16];
#pragma unroll
                for (int i = 0; i < 8; i++) {
                    float4 av = *(const float4*)(arow + i * 4);
                    float4 bv = *(const float4*)(bmp + i * 4);
                    float y0 = fmaxf(av.x + bv.x, 0.f);
                    float y1 = fmaxf(av.y + bv.y, 0.f);
                    float y2 = fmaxf(av.z + bv.z, 0.f);
                    float y3 = fmaxf(av.w + bv.w, 0.f);
                    split2(y0, y1, hw[2 * i], lw[2 * i]);
                    split2(y2, y3, hw[2 * i + 1], lw[2 * i + 1]);
                }
                uint32_t ro = (uint32_t)(lr * TP + half * 64);
#pragma unroll
                for (int j = 0; j < 4; j++) {
                    *(uint4*)(smc + SM_HHI + ro + j * 16) =
                        make_uint4(hw[4 * j], hw[4 * j + 1], hw[4 * j + 2], hw[4 * j + 3]);
                    *(uint4*)(smc + SM_HLO + ro + j * 16) =
                        make_uint4(lw[4 * j], lw[4 * j + 1], lw[4 * j + 2], lw[4 * j + 3]);
                }
            }
            // load W1 chunk rows [nh*128 + 0..127], cols [kc*64 ..+64)
            {
                const uint4* sh = (const uint4*)(w1h + (size_t)(nh * 128 + lr) * 256 + kc * 64 + half * 32);
                const uint4* sl = (const uint4*)(w1l + (size_t)(nh * 128 + lr) * 256 + kc * 64 + half * 32);
                uint32_t ro = (uint32_t)(lr * TP + half * 64);
#pragma unroll
                for (int j = 0; j < 4; j++) {
                    *(uint4*)(smc + SM_WHI + ro + j * 16) = sh[j];
                    *(uint4*)(smc + SM_WLO + ro + j * 16) = sl[j];
                }
            }
            __syncthreads();
            gemm_chunk(smem_base, w, lane, acc1);
        }

        // ---------- Layer 2 partial: consume Y1 half as two K-chunks ----------
        for (int c2 = 0; c2 < 2; c2++) {
            int k2 = nh * 2 + c2;     // layer2 K-chunk index 0..3
            __syncthreads();          // Hbuf/Wbuf free
            // store Y1 chunk (tiles c2*8 .. +8) from acc1: bias+relu+split
#pragma unroll
            for (int tl = 0; tl < 8; tl++) {
                int tile = c2 * 8 + tl;
                int colg = nh * 128 + tile * 8 + tg * 2;
                float y0 = fmaxf(acc1[tile][0] + b1s[colg],     0.f);
                float y1 = fmaxf(acc1[tile][1] + b1s[colg + 1], 0.f);
                float y2 = fmaxf(acc1[tile][2] + b1s[colg],     0.f);
                float y3 = fmaxf(acc1[tile][3] + b1s[colg + 1], 0.f);
                uint32_t hw0, lw0, hw1, lw1;
                split2(y0, y1, hw0, lw0);
                split2(y2, y3, hw1, lw1);
                uint32_t o0 = (uint32_t)((16 * w + g) * TP + (tl * 8 + tg * 2) * 2);
                uint32_t o1 = o0 + 8 * TP;
                *(uint32_t*)(smc + SM_HHI + o0) = hw0;
                *(uint32_t*)(smc + SM_HLO + o0) = lw0;
                *(uint32_t*)(smc + SM_HHI + o1) = hw1;
                *(uint32_t*)(smc + SM_HLO + o1) = lw1;
            }
            // load W2 chunk rows 0..127, cols [k2*64 ..+64)
            {
                const uint4* sh = (const uint4*)(w2h + (size_t)lr * 256 + k2 * 64 + half * 32);
                const uint4* sl = (const uint4*)(w2l + (size_t)lr * 256 + k2 * 64 + half * 32);
                uint32_t ro = (uint32_t)(lr * TP + half * 64);
#pragma unroll
                for (int j = 0; j < 4; j++) {
                    *(uint4*)(smc + SM_WHI + ro + j * 16) = sh[j];
                    *(uint4*)(smc + SM_WLO + ro + j * 16) = sl[j];
                }
            }
            __syncthreads();
            gemm_chunk(smem_base, w, lane, acc2);
        }
    }

    // ---------- epilogue: relu(D2+b2), sum over j, write msg ----------
#pragma unroll
    for (int tile = 0; tile < 16; tile++) {
        int c0 = tile * 8 + tg * 2;
        float v0 = fmaxf(acc2[tile][0] + b2s[c0], 0.f) +
                   fmaxf(acc2[tile][2] + b2s[c0], 0.f);
        float v1 = fmaxf(acc2[tile][1] + b2s[c0 + 1], 0.f) +
                   fmaxf(acc2[tile][3] + b2s[c0 + 1], 0.f);
#pragma unroll
        for (int o = 4; o < 32; o <<= 1) {
            v0 += __shfl_xor_sync(0xFFFFFFFFu, v0, o);
            v1 += __shfl_xor_sync(0xFFFFFFFFu, v1, o);
        }
        if (lane < 4) {
            red[w * 128 + c0] = v0;
            red[w * 128 + c0 + 1] = v1;
        }
    }
    __syncthreads();
    if (t < 128) {
        float s = 0.f;
#pragma unroll
        for (int ww = 0; ww < 8; ww++) s += red[ww * 128 + t];
        gmsg[(size_t)row * 128 + t] = s;
    }
}

// ---------------------------------------------------------------------------
// Generic tiled linear:  C[M,N] = X[M,K] @ W[N, ldw]^T (+bias) (+=C) (relu)
// ---------------------------------------------------------------------------
__global__ __launch_bounds__(256) void linear_kernel(
    const float* __restrict__ Xp, int xo,
    const float* __restrict__ W, const float* __restrict__ bias,
    float* __restrict__ Cp, int co,
    int M, int Nout, int K, int ldw, int do_relu, int do_acc)
{
    const float* X = Xp ? Xp : (const float*)(g_scratch + xo);
    float* C = Cp ? Cp : (g_scratch + co);

    __shared__ float Xs[16 * 64];
    __shared__ float Wsm[16 * 64];

    int t  = threadIdx.x;
    int m0 = blockIdx.y * 64;
    int n0 = blockIdx.x * 64;
    int mt = t >> 4;
    int nt = t & 15;

    float acc[4][4];
#pragma unroll
    for (int r = 0; r < 4; r++)
#pragma unroll
        for (int c = 0; c < 4; c++) acc[r][c] = 0.f;

    int lm = t >> 2;
    int lk = (t & 3) * 4;

    for (int k0 = 0; k0 < K; k0 += 16) {
        float4 xv = make_float4(0.f, 0.f, 0.f, 0.f);
        float4 wv = make_float4(0.f, 0.f, 0.f, 0.f);
        if (m0 + lm < M) xv = *(const float4*)&X[(size_t)(m0 + lm) * K + k0 + lk];
        if (n0 + lm < Nout) wv = *(const float4*)&W[(size_t)(n0 + lm) * ldw + k0 + lk];
        Xs[(lk + 0) * 64 + lm] = xv.x;
        Xs[(lk + 1) * 64 + lm] = xv.y;
        Xs[(lk + 2) * 64 + lm] = xv.z;
        Xs[(lk + 3) * 64 + lm] = xv.w;
        Wsm[(lk + 0) * 64 + lm] = wv.x;
        Wsm[(lk + 1) * 64 + lm] = wv.y;
        Wsm[(lk + 2) * 64 + lm] = wv.z;
        Wsm[(lk + 3) * 64 + lm] = wv.w;
        __syncthreads();
#pragma unroll
        for (int kk = 0; kk < 16; kk++) {
            float4 a = *(const float4*)&Xs[kk * 64 + mt * 4];
            float4 bb = *(const float4*)&Wsm[kk * 64 + nt * 4];
            float av[4] = {a.x, a.y, a.z, a.w};
            float bv[4] = {bb.x, bb.y, bb.z, bb.w};
#pragma unroll
            for (int r = 0; r < 4; r++)
#pragma unroll
                for (int c = 0; c < 4; c++) acc[r][c] += av[r] * bv[c];
        }
        __syncthreads();
    }

#pragma unroll
    for (int r = 0; r < 4; r++) {
        int rw = m0 + mt * 4 + r;
        if (rw >= M) continue;
#pragma unroll
        for (int c = 0; c < 4; c++) {
            int col = n0 + nt * 4 + c;
            if (col >= Nout) continue;
            float v = acc[r][c];
            if (bias) v += bias[col];
            if (do_acc) v += C[(size_t)rw * Nout + col];
            if (do_relu) v = fmaxf(v, 0.f);
            C[(size_t)rw * Nout + col] = v;
        }
    }
}

// ---------------------------------------------------------------------------
// small helpers
// ---------------------------------------------------------------------------
__global__ void pack_kernel(const float* __restrict__ x)
{
    float* gin = g_scratch + OFF_GIN;
    const float* msg = g_scratch + OFF_MSG;
    int r = blockIdx.x;
    int t = threadIdx.x;
    if (t < 128) gin[r * 256 + t] = x[r * 128 + t];
    else         gin[r * 256 + t] = msg[r * 128 + (t - 128)];
}

__device__ __forceinline__ float sigf(float v) { return 1.f / (1.f + expf(-v)); }

__global__ void lstm_kernel(const float* __restrict__ c0, float* __restrict__ out)
{
    const float* gates = g_scratch + OFF_GATES;
    int idx = blockIdx.x * blockDim.x + threadIdx.x;
    int r = idx >> 7;
    int m = idx & 127;
    float ig = gates[r * 512 + m];
    float fg = gates[r * 512 + 128 + m];
    float gg = gates[r * 512 + 256 + m];
    float og = gates[r * 512 + 384 + m];
    float c = sigf(fg) * c0[idx] + sigf(ig) * tanhf(gg);
    float h = sigf(og) * tanhf(c);
    out[OUT_OG + idx] = h;
    out[OUT_H + idx] = h;
    out[OUT_C + idx] = c;
}

__global__ void sumhid_kernel(const float* __restrict__ out)
{
    float* sumh = g_scratch + OFF_SUMH;
    int b = blockIdx.x;
    int m = threadIdx.x;
    float s = 0.f;
    for (int n = 0; n < 128; n++)
        s += out[OUT_OG + (b * 128 + n) * 128 + m];
    sumh[b * 128 + m] = s;
}

// ---------------------------------------------------------------------------
// launch
// ---------------------------------------------------------------------------
extern "C" void kernel_launch(void* const* d_in, const int* in_sizes, int n_in,
                              void* d_out, int out_size)
{
    const float* x        = (const float*)d_in[0];
    const float* hidden   = (const float*)d_in[1];
    const float* h0       = (const float*)d_in[2];
    const float* c0       = (const float*)d_in[3];
    const float* f_w0     = (const float*)d_in[4];
    const float* f_b0     = (const float*)d_in[5];
    const float* f_w1     = (const float*)d_in[6];
    const float* f_b1     = (const float*)d_in[7];
    const float* f_w2     = (const float*)d_in[8];
    const float* f_b2     = (const float*)d_in[9];
    const float* g_w0     = (const float*)d_in[10];
    const float* g_b0     = (const float*)d_in[11];
    const float* g_w1     = (const float*)d_in[12];
    const float* g_b1     = (const float*)d_in[13];
    const float* g_w2     = (const float*)d_in[14];
    const float* g_b2     = (const float*)d_in[15];
    const float* lstm_wih = (const float*)d_in[16];
    const float* lstm_whh = (const float*)d_in[17];
    const float* lstm_bih = (const float*)d_in[18];
    const float* lstm_bhh = (const float*)d_in[19];
    const float* o_w0     = (const float*)d_in[20];
    const float* o_b0     = (const float*)d_in[21];
    const float* o_w1     = (const float*)d_in[22];
    const float* o_b1     = (const float*)d_in[23];
    float* out = (float*)d_out;

    static int smem_set = 0;
    if (!smem_set) {
        cudaFuncSetAttribute(msg_kernel, cudaFuncAttributeMaxDynamicSharedMemorySize, MSG_SMEM);
        smem_set = 1;
    }

    dim3 blk(256);

    // weight hi/lo split (bf16) for tensor-core pair-MLP
    wsplit_kernel<<<256, 256>>>(f_w1, f_w2);

    // layer0 factorization: A = hidden @ W0[:, :128]^T ; Bm = hidden @ W0[:,128:]^T + b0
    linear_kernel<<<dim3(4, 32), blk>>>(hidden, 0, f_w0,       nullptr, nullptr, OFF_A,  R_, 256, 128, 256, 0, 0);
    linear_kernel<<<dim3(4, 32), blk>>>(hidden, 0, f_w0 + 128, f_b0,    nullptr, OFF_BM, R_, 256, 128, 256, 0, 0);

    // fused pair-MLP + source sum (mma.sync bf16 hi/lo)
    msg_kernel<<<R_, blk, MSG_SMEM>>>(f_b1, f_b2);

    // g-MLP
    pack_kernel<<<R_, blk>>>(x);
    linear_kernel<<<dim3(4, 32), blk>>>(nullptr, OFF_GIN, g_w0, g_b0, nullptr, OFF_T1,  R_, 256, 256, 256, 1, 0);
    linear_kernel<<<dim3(4, 32), blk>>>(nullptr, OFF_T1,  g_w1, g_b1, nullptr, OFF_T2,  R_, 256, 256, 256, 1, 0);
    linear_kernel<<<dim3(2, 32), blk>>>(nullptr, OFF_T2,  g_w2, g_b2, nullptr, OFF_INP, R_, 128, 256, 256, 1, 0);

    // LSTM gates = inp @ wih^T + bih + h0 @ whh^T + bhh
    linear_kernel<<<dim3(8, 32), blk>>>(nullptr, OFF_INP, lstm_wih, lstm_bih, nullptr, OFF_GATES, R_, 512, 128, 128, 0, 0);
    linear_kernel<<<dim3(8, 32), blk>>>(h0, 0,            lstm_whh, lstm_bhh, nullptr, OFF_GATES, R_, 512, 128, 128, 0, 1);
    lstm_kernel<<<1024, 256>>>(c0, out);

    // output head
    sumhid_kernel<<<16, 128>>>(out);
    linear_kernel<<<dim3(4, 1), blk>>>(nullptr, OFF_SUMH, o_w0, o_b0, nullptr, OFF_O0, 16, 256, 128, 128, 1, 0);
    linear_kernel<<<dim3(1, 1), blk>>>(nullptr, OFF_O0,   o_w1, o_b1, out, 0,          16, 64,  256, 256, 1, 0);
}

// round 8
// speedup vs baseline: 1.8925x; 1.5812x over previous
#include <cuda_runtime.h>
#include <cuda_bf16.h>
#include <stdint.h>
#include <math.h>

// ---------------------------------------------------------------------------
// Shapes: B=16, N=128, H=128, M=128.  R = B*N = 2048 rows.
// Pair MLP: 256 -> 256 -> 256 -> 128 (relu each), summed over source j.
// Round 8: mma.sync bf16 hi/lo 3-pass; 4x2 warp blocking; cp.async
// double-buffered weight tiles; SMEM-staged Y1; reduced register staging.
// ---------------------------------------------------------------------------

#define R_ 2048

// ------------------------- device scratch (no allocs) ----------------------
__device__ float g_scratch[4298752];
#define OFF_A     0          // [2048][256] fp32
#define OFF_BM    524288     // [2048][256] fp32 (includes f_b0)
#define OFF_MSG   1048576    // [2048][128]
#define OFF_GIN   1310720    // [2048][256]
#define OFF_T1    1835008    // [2048][256]
#define OFF_T2    2359296    // [2048][256]
#define OFF_INP   2883584    // [2048][128]
#define OFF_GATES 3145728    // [2048][512]
#define OFF_SUMH  4194304    // [16][128]
#define OFF_O0    4196352    // [16][256]
#define OFF_W1HI  4200448    // 65536 bf16
#define OFF_W1LO  4233216
#define OFF_W2HI  4265984    // 32768 bf16
#define OFF_W2LO  4282368

// output layout (floats): out[16*64], out_g[2048*128], h_n[2048*128], c_n[2048*128]
#define OUT_OG 1024
#define OUT_H  263168
#define OUT_C  525312

// =========================== asm helpers ====================================
__device__ __forceinline__ uint32_t s2u(const void* p) {
    uint32_t a;
    asm("{ .reg .u64 t; cvta.to.shared.u64 t, %1; cvt.u32.u64 %0, t; }"
        : "=r"(a) : "l"(p));
    return a;
}

#define LDSM4(r, addr) \
    asm volatile("ldmatrix.sync.aligned.m8n8.x4.shared.b16 {%0,%1,%2,%3}, [%4];" \
        : "=r"((r)[0]), "=r"((r)[1]), "=r"((r)[2]), "=r"((r)[3]) : "r"(addr))

#define MMA16816(d, a, b0_, b1_) \
    asm volatile("mma.sync.aligned.m16n8k16.row.col.f32.bf16.bf16.f32 " \
        "{%0,%1,%2,%3}, {%4,%5,%6,%7}, {%8,%9}, {%0,%1,%2,%3};" \
        : "+f"((d)[0]), "+f"((d)[1]), "+f"((d)[2]), "+f"((d)[3]) \
        : "r"((a)[0]), "r"((a)[1]), "r"((a)[2]), "r"((a)[3]), \
          "r"(b0_), "r"(b1_))

#define CP16(d, s) \
    asm volatile("cp.async.cg.shared.global [%0], [%1], 16;" :: "r"(d), "l"(s))
#define CPCOMMIT() asm volatile("cp.async.commit_group;" ::: "memory")
#define CPWAIT1()  asm volatile("cp.async.wait_group 1;" ::: "memory")
#define CPWAIT0()  asm volatile("cp.async.wait_group 0;" ::: "memory")

__device__ __forceinline__ void split2(float y0, float y1,
                                       uint32_t& hw, uint32_t& lw) {
    __nv_bfloat16 h0 = __float2bfloat16(y0);
    __nv_bfloat16 h1 = __float2bfloat16(y1);
    float l0 = y0 - __bfloat162float(h0);
    float l1 = y1 - __bfloat162float(h1);
    hw = (uint32_t)__bfloat16_as_ushort(h0) |
         ((uint32_t)__bfloat16_as_ushort(h1) << 16);
    lw = (uint32_t)__bfloat16_as_ushort(__float2bfloat16(l0)) |
         ((uint32_t)__bfloat16_as_ushort(__float2bfloat16(l1)) << 16);
}

// ---------------------------------------------------------------------------
// Weight split prep
// ---------------------------------------------------------------------------
__global__ void wsplit_kernel(const float* __restrict__ W1,
                              const float* __restrict__ W2)
{
    int i = blockIdx.x * blockDim.x + threadIdx.x;
    __nv_bfloat16* w1h = (__nv_bfloat16*)(g_scratch + OFF_W1HI);
    __nv_bfloat16* w1l = (__nv_bfloat16*)(g_scratch + OFF_W1LO);
    __nv_bfloat16* w2h = (__nv_bfloat16*)(g_scratch + OFF_W2HI);
    __nv_bfloat16* w2l = (__nv_bfloat16*)(g_scratch + OFF_W2LO);
    if (i < 65536) {
        float w = W1[i];
        __nv_bfloat16 h = __float2bfloat16(w);
        w1h[i] = h;
        w1l[i] = __float2bfloat16(w - __bfloat162float(h));
    }
    if (i < 32768) {
        float w = W2[i];
        __nv_bfloat16 h = __float2bfloat16(w);
        w2h[i] = h;
        w2l[i] = __float2bfloat16(w - __bfloat162float(h));
    }
}

// ---------------------------------------------------------------------------
// SMEM layout (bytes)
// ---------------------------------------------------------------------------
#define TP 144            // 64-col tile row pitch (128B data + 16 pad)
#define YP 272            // 128-col Y tile row pitch (256B data + 16 pad)
#define SM_RED   0        // 4*128 f32 = 2048
#define SM_B1    2048     // 256 f32
#define SM_B2    3072     // 128 f32
#define SM_BM    3584     // 256 f32
#define SM_HHI   4608     // 128*144
#define SM_HLO   23040
#define SM_W0HI  41472
#define SM_W0LO  59904
#define SM_W1HI  78336
#define SM_W1LO  96768
#define SM_YHI   115200   // 128*272
#define SM_YLO   150016
#define MSG_SMEM 184832
#define WLODELTA 18432

// One 64-wide K-chunk: acc[2][8][4] += A(32 rows) x B(64 cols), 3-pass hi/lo.
__device__ __forceinline__ void gemm_chunk2(
    const char* smc, uint32_t smem_base,
    uint32_t aHiOff, uint32_t aLoOff, int apitch, int acolByte,
    uint32_t bHiOff,
    float (*acc)[8][4], int mg, int ng, int lane)
{
    uint32_t aoff0 = smem_base + aHiOff +
        (uint32_t)((mg * 32 + (lane & 15)) * apitch + acolByte + (((lane >> 4) << 3) << 1));
    uint32_t adelta = aLoOff - aHiOff;
    uint32_t boff0 = smem_base + bHiOff +
        (uint32_t)((ng * 64 + (lane & 7) + ((lane >> 4) << 3)) * TP + ((((lane >> 3) & 1) << 3) << 1));
#pragma unroll
    for (int ks = 0; ks < 4; ks++) {
        uint32_t ah[2][4], al[2][4];
#pragma unroll
        for (int mt = 0; mt < 2; mt++) {
            uint32_t ad = aoff0 + (uint32_t)(mt * 16 * apitch + ks * 32);
            LDSM4(ah[mt], ad);
            LDSM4(al[mt], ad + adelta);
        }
#pragma unroll
        for (int ntp = 0; ntp < 4; ntp++) {
            uint32_t bd = boff0 + (uint32_t)(ntp * 16 * TP + ks * 32);
            uint32_t bh[4], bl[4];
            LDSM4(bh, bd);
            LDSM4(bl, bd + WLODELTA);
#pragma unroll
            for (int mt = 0; mt < 2; mt++) {
                MMA16816(acc[mt][2 * ntp],     ah[mt], bh[0], bh[1]);
                MMA16816(acc[mt][2 * ntp + 1], ah[mt], bh[2], bh[3]);
                MMA16816(acc[mt][2 * ntp],     ah[mt], bl[0], bl[1]);
                MMA16816(acc[mt][2 * ntp + 1], ah[mt], bl[2], bl[3]);
                MMA16816(acc[mt][2 * ntp],     al[mt], bh[0], bh[1]);
                MMA16816(acc[mt][2 * ntp + 1], al[mt], bh[2], bh[3]);
            }
        }
    }
}

// ---------------------------------------------------------------------------
// Fused pair-MLP + source-sum. One CTA per (b,i), 256 thr, 8 warps (4mg x 2ng).
// ---------------------------------------------------------------------------
__global__ __launch_bounds__(256, 1) void msg_kernel(
    const float* __restrict__ b1g, const float* __restrict__ b2g)
{
    extern __shared__ char smc[];
    const uint32_t smem_base = s2u(smc);

    const float* gA  = g_scratch + OFF_A;
    const float* gBm = g_scratch + OFF_BM;
    float* gmsg      = g_scratch + OFF_MSG;
    const __nv_bfloat16* w1h = (const __nv_bfloat16*)(g_scratch + OFF_W1HI);
    const __nv_bfloat16* w1l = (const __nv_bfloat16*)(g_scratch + OFF_W1LO);
    const __nv_bfloat16* w2h = (const __nv_bfloat16*)(g_scratch + OFF_W2HI);
    const __nv_bfloat16* w2l = (const __nv_bfloat16*)(g_scratch + OFF_W2LO);

    float* red = (float*)(smc + SM_RED);
    float* b1s = (float*)(smc + SM_B1);
    float* b2s = (float*)(smc + SM_B2);
    float* Bms = (float*)(smc + SM_BM);

    int t    = threadIdx.x;
    int w    = t >> 5;
    int lane = t & 31;
    int mg   = w >> 1;          // 0..3 : 32-row group
    int ng   = w & 1;           // 0..1 : 64-col group
    int g    = lane >> 2;       // 0..7
    int tg   = lane & 3;        // 0..3
    int row  = blockIdx.x;      // b*128 + i
    int b    = row >> 7;
    int lr   = t >> 1;          // loader row 0..127
    int hf   = t & 1;           // loader col half

    b1s[t] = b1g[t];
    if (t < 128) b2s[t] = b2g[t];
    Bms[t] = gBm[(size_t)row * 256 + t];

    float acc2[2][8][4];
#pragma unroll
    for (int mt = 0; mt < 2; mt++)
#pragma unroll
        for (int i = 0; i < 8; i++)
#pragma unroll
            for (int c = 0; c < 4; c++) acc2[mt][i][c] = 0.f;

    // weight-chunk prefetch: 12 loads, alternating W buffers
    auto issue_load = [&](int li) {
        int h = li >= 6;
        int s = li - h * 6;
        const __nv_bfloat16 *sh, *sl;
        if (s < 4) {
            sh = w1h + (size_t)(h * 128 + lr) * 256 + s * 64 + hf * 32;
            sl = w1l + (size_t)(h * 128 + lr) * 256 + s * 64 + hf * 32;
        } else {
            int k2 = h * 2 + (s - 4);
            sh = w2h + (size_t)lr * 256 + k2 * 64 + hf * 32;
            sl = w2l + (size_t)lr * 256 + k2 * 64 + hf * 32;
        }
        uint32_t d = smem_base + ((li & 1) ? SM_W1HI : SM_W0HI) + lr * TP + hf * 64;
#pragma unroll
        for (int j = 0; j < 4; j++) CP16(d + j * 16, sh + j * 8);
        d += WLODELTA;
#pragma unroll
        for (int j = 0; j < 4; j++) CP16(d + j * 16, sl + j * 8);
        CPCOMMIT();
    };

    issue_load(0);

    for (int h = 0; h < 2; h++) {
        float acc1[2][8][4];
#pragma unroll
        for (int mt = 0; mt < 2; mt++)
#pragma unroll
            for (int i = 0; i < 8; i++)
#pragma unroll
                for (int c = 0; c < 4; c++) acc1[mt][i][c] = 0.f;

        // -------- layer 1: acc1 += H0 @ W1[half h]^T --------
        for (int kc = 0; kc < 4; kc++) {
            int li = h * 6 + kc;
            __syncthreads();                       // prev MMA done: H + other W buf free
            if (li + 1 < 12) issue_load(li + 1);
            // build H0 chunk: relu(A + Bm), split hi/lo, immediate stores
            {
                const float* arow = gA + (size_t)(b * 128 + lr) * 256 + kc * 64 + hf * 32;
                const float* bmp  = Bms + kc * 64 + hf * 32;
                uint32_t ro = (uint32_t)(lr * TP + hf * 64);
#pragma unroll
                for (int i = 0; i < 8; i++) {
                    float4 av = *(const float4*)(arow + i * 4);
                    float4 bv = *(const float4*)(bmp + i * 4);
                    float y0 = fmaxf(av.x + bv.x, 0.f);
                    float y1 = fmaxf(av.y + bv.y, 0.f);
                    float y2 = fmaxf(av.z + bv.z, 0.f);
                    float y3 = fmaxf(av.w + bv.w, 0.f);
                    uint32_t hw0, lw0, hw1, lw1;
                    split2(y0, y1, hw0, lw0);
                    split2(y2, y3, hw1, lw1);
                    *(uint2*)(smc + SM_HHI + ro + i * 8) = make_uint2(hw0, hw1);
                    *(uint2*)(smc + SM_HLO + ro + i * 8) = make_uint2(lw0, lw1);
                }
            }
            if (li + 1 < 12) { CPWAIT1(); } else { CPWAIT0(); }
            __syncthreads();
            gemm_chunk2(smc, smem_base, SM_HHI, SM_HLO, TP, 0,
                        (li & 1) ? SM_W1HI : SM_W0HI, acc1, mg, ng, lane);
        }

        // -------- Y1 store + layer 2 chunks --------
        for (int c2 = 0; c2 < 2; c2++) {
            int li = h * 6 + 4 + c2;
            __syncthreads();
            if (li + 1 < 12) issue_load(li + 1);
            if (c2 == 0) {
                // store full 128x128 Y1 half: bias+relu+split from acc1
#pragma unroll
                for (int mt = 0; mt < 2; mt++) {
                    int r0 = mg * 32 + mt * 16 + g;
#pragma unroll
                    for (int nt = 0; nt < 8; nt++) {
                        int lcol = ng * 64 + nt * 8 + tg * 2;
                        int gcol = h * 128 + lcol;
                        float bia = b1s[gcol], bib = b1s[gcol + 1];
                        float y0 = fmaxf(acc1[mt][nt][0] + bia, 0.f);
                        float y1 = fmaxf(acc1[mt][nt][1] + bib, 0.f);
                        float y2 = fmaxf(acc1[mt][nt][2] + bia, 0.f);
                        float y3 = fmaxf(acc1[mt][nt][3] + bib, 0.f);
                        uint32_t hw0, lw0, hw1, lw1;
                        split2(y0, y1, hw0, lw0);
                        split2(y2, y3, hw1, lw1);
                        *(uint32_t*)(smc + SM_YHI + r0 * YP + lcol * 2) = hw0;
                        *(uint32_t*)(smc + SM_YLO + r0 * YP + lcol * 2) = lw0;
                        *(uint32_t*)(smc + SM_YHI + (r0 + 8) * YP + lcol * 2) = hw1;
                        *(uint32_t*)(smc + SM_YLO + (r0 + 8) * YP + lcol * 2) = lw1;
                    }
                }
            }
            if (li + 1 < 12) { CPWAIT1(); } else { CPWAIT0(); }
            __syncthreads();
            gemm_chunk2(smc, smem_base, SM_YHI, SM_YLO, YP, c2 * 128,
                        (li & 1) ? SM_W1HI : SM_W0HI, acc2, mg, ng, lane);
        }
    }

    // -------- epilogue: relu(D2+b2), sum over j, write msg --------
#pragma unroll
    for (int nt = 0; nt < 8; nt++) {
        int lcol = ng * 64 + nt * 8 + tg * 2;
        float bia = b2s[lcol], bib = b2s[lcol + 1];
        float v0 = 0.f, v1 = 0.f;
#pragma unroll
        for (int mt = 0; mt < 2; mt++) {
            v0 += fmaxf(acc2[mt][nt][0] + bia, 0.f) + fmaxf(acc2[mt][nt][2] + bia, 0.f);
            v1 += fmaxf(acc2[mt][nt][1] + bib, 0.f) + fmaxf(acc2[mt][nt][3] + bib, 0.f);
        }
#pragma unroll
        for (int o = 4; o < 32; o <<= 1) {
            v0 += __shfl_xor_sync(0xFFFFFFFFu, v0, o);
            v1 += __shfl_xor_sync(0xFFFFFFFFu, v1, o);
        }
        if (lane < 4) {
            red[mg * 128 + lcol] = v0;
            red[mg * 128 + lcol + 1] = v1;
        }
    }
    __syncthreads();
    if (t < 128)
        gmsg[(size_t)row * 128 + t] =
            red[t] + red[128 + t] + red[256 + t] + red[384 + t];
}

// ---------------------------------------------------------------------------
// Generic tiled linear:  C[M,N] = X[M,K] @ W[N, ldw]^T (+bias) (+=C) (relu)
// ---------------------------------------------------------------------------
__global__ __launch_bounds__(256) void linear_kernel(
    const float* __restrict__ Xp, int xo,
    const float* __restrict__ W, const float* __restrict__ bias,
    float* __restrict__ Cp, int co,
    int M, int Nout, int K, int ldw, int do_relu, int do_acc)
{
    const float* X = Xp ? Xp : (const float*)(g_scratch + xo);
    float* C = Cp ? Cp : (g_scratch + co);

    __shared__ float Xs[16 * 64];
    __shared__ float Wsm[16 * 64];

    int t  = threadIdx.x;
    int m0 = blockIdx.y * 64;
    int n0 = blockIdx.x * 64;
    int mt = t >> 4;
    int nt = t & 15;

    float acc[4][4];
#pragma unroll
    for (int r = 0; r < 4; r++)
#pragma unroll
        for (int c = 0; c < 4; c++) acc[r][c] = 0.f;

    int lm = t >> 2;
    int lk = (t & 3) * 4;

    for (int k0 = 0; k0 < K; k0 += 16) {
        float4 xv = make_float4(0.f, 0.f, 0.f, 0.f);
        float4 wv = make_float4(0.f, 0.f, 0.f, 0.f);
        if (m0 + lm < M) xv = *(const float4*)&X[(size_t)(m0 + lm) * K + k0 + lk];
        if (n0 + lm < Nout) wv = *(const float4*)&W[(size_t)(n0 + lm) * ldw + k0 + lk];
        Xs[(lk + 0) * 64 + lm] = xv.x;
        Xs[(lk + 1) * 64 + lm] = xv.y;
        Xs[(lk + 2) * 64 + lm] = xv.z;
        Xs[(lk + 3) * 64 + lm] = xv.w;
        Wsm[(lk + 0) * 64 + lm] = wv.x;
        Wsm[(lk + 1) * 64 + lm] = wv.y;
        Wsm[(lk + 2) * 64 + lm] = wv.z;
        Wsm[(lk + 3) * 64 + lm] = wv.w;
        __syncthreads();
#pragma unroll
        for (int kk = 0; kk < 16; kk++) {
            float4 a = *(const float4*)&Xs[kk * 64 + mt * 4];
            float4 bb = *(const float4*)&Wsm[kk * 64 + nt * 4];
            float av[4] = {a.x, a.y, a.z, a.w};
            float bv[4] = {bb.x, bb.y, bb.z, bb.w};
#pragma unroll
            for (int r = 0; r < 4; r++)
#pragma unroll
                for (int c = 0; c < 4; c++) acc[r][c] += av[r] * bv[c];
        }
        __syncthreads();
    }

#pragma unroll
    for (int r = 0; r < 4; r++) {
        int rw = m0 + mt * 4 + r;
        if (rw >= M) continue;
#pragma unroll
        for (int c = 0; c < 4; c++) {
            int col = n0 + nt * 4 + c;
            if (col >= Nout) continue;
            float v = acc[r][c];
            if (bias) v += bias[col];
            if (do_acc) v += C[(size_t)rw * Nout + col];
            if (do_relu) v = fmaxf(v, 0.f);
            C[(size_t)rw * Nout + col] = v;
        }
    }
}

// ---------------------------------------------------------------------------
// small helpers
// ---------------------------------------------------------------------------
__global__ void pack_kernel(const float* __restrict__ x)
{
    float* gin = g_scratch + OFF_GIN;
    const float* msg = g_scratch + OFF_MSG;
    int r = blockIdx.x;
    int t = threadIdx.x;
    if (t < 128) gin[r * 256 + t] = x[r * 128 + t];
    else         gin[r * 256 + t] = msg[r * 128 + (t - 128)];
}

__device__ __forceinline__ float sigf(float v) { return 1.f / (1.f + expf(-v)); }

__global__ void lstm_kernel(const float* __restrict__ c0, float* __restrict__ out)
{
    const float* gates = g_scratch + OFF_GATES;
    int idx = blockIdx.x * blockDim.x + threadIdx.x;
    int r = idx >> 7;
    int m = idx & 127;
    float ig = gates[r * 512 + m];
    float fg = gates[r * 512 + 128 + m];
    float gg = gates[r * 512 + 256 + m];
    float og = gates[r * 512 + 384 + m];
    float c = sigf(fg) * c0[idx] + sigf(ig) * tanhf(gg);
    float h = sigf(og) * tanhf(c);
    out[OUT_OG + idx] = h;
    out[OUT_H + idx] = h;
    out[OUT_C + idx] = c;
}

__global__ void sumhid_kernel(const float* __restrict__ out)
{
    float* sumh = g_scratch + OFF_SUMH;
    int b = blockIdx.x;
    int m = threadIdx.x;
    float s = 0.f;
    for (int n = 0; n < 128; n++)
        s += out[OUT_OG + (b * 128 + n) * 128 + m];
    sumh[b * 128 + m] = s;
}

// ---------------------------------------------------------------------------
// launch
// ---------------------------------------------------------------------------
extern "C" void kernel_launch(void* const* d_in, const int* in_sizes, int n_in,
                              void* d_out, int out_size)
{
    const float* x        = (const float*)d_in[0];
    const float* hidden   = (const float*)d_in[1];
    const float* h0       = (const float*)d_in[2];
    const float* c0       = (const float*)d_in[3];
    const float* f_w0     = (const float*)d_in[4];
    const float* f_b0     = (const float*)d_in[5];
    const float* f_w1     = (const float*)d_in[6];
    const float* f_b1     = (const float*)d_in[7];
    const float* f_w2     = (const float*)d_in[8];
    const float* f_b2     = (const float*)d_in[9];
    const float* g_w0     = (const float*)d_in[10];
    const float* g_b0     = (const float*)d_in[11];
    const float* g_w1     = (const float*)d_in[12];
    const float* g_b1     = (const float*)d_in[13];
    const float* g_w2     = (const float*)d_in[14];
    const float* g_b2     = (const float*)d_in[15];
    const float* lstm_wih = (const float*)d_in[16];
    const float* lstm_whh = (const float*)d_in[17];
    const float* lstm_bih = (const float*)d_in[18];
    const float* lstm_bhh = (const float*)d_in[19];
    const float* o_w0     = (const float*)d_in[20];
    const float* o_b0     = (const float*)d_in[21];
    const float* o_w1     = (const float*)d_in[22];
    const float* o_b1     = (const float*)d_in[23];
    float* out = (float*)d_out;

    static int smem_set = 0;
    if (!smem_set) {
        cudaFuncSetAttribute(msg_kernel, cudaFuncAttributeMaxDynamicSharedMemorySize, MSG_SMEM);
        smem_set = 1;
    }

    dim3 blk(256);

    // weight hi/lo split (bf16) for tensor-core pair-MLP
    wsplit_kernel<<<256, 256>>>(f_w1, f_w2);

    // layer0 factorization: A = hidden @ W0[:, :128]^T ; Bm = hidden @ W0[:,128:]^T + b0
    linear_kernel<<<dim3(4, 32), blk>>>(hidden, 0, f_w0,       nullptr, nullptr, OFF_A,  R_, 256, 128, 256, 0, 0);
    linear_kernel<<<dim3(4, 32), blk>>>(hidden, 0, f_w0 + 128, f_b0,    nullptr, OFF_BM, R_, 256, 128, 256, 0, 0);

    // fused pair-MLP + source sum (mma.sync bf16 hi/lo)
    msg_kernel<<<R_, blk, MSG_SMEM>>>(f_b1, f_b2);

    // g-MLP
    pack_kernel<<<R_, blk>>>(x);
    linear_kernel<<<dim3(4, 32), blk>>>(nullptr, OFF_GIN, g_w0, g_b0, nullptr, OFF_T1,  R_, 256, 256, 256, 1, 0);
    linear_kernel<<<dim3(4, 32), blk>>>(nullptr, OFF_T1,  g_w1, g_b1, nullptr, OFF_T2,  R_, 256, 256, 256, 1, 0);
    linear_kernel<<<dim3(2, 32), blk>>>(nullptr, OFF_T2,  g_w2, g_b2, nullptr, OFF_INP, R_, 128, 256, 256, 1, 0);

    // LSTM gates = inp @ wih^T + bih + h0 @ whh^T + bhh
    linear_kernel<<<dim3(8, 32), blk>>>(nullptr, OFF_INP, lstm_wih, lstm_bih, nullptr, OFF_GATES, R_, 512, 128, 128, 0, 0);
    linear_kernel<<<dim3(8, 32), blk>>>(h0, 0,            lstm_whh, lstm_bhh, nullptr, OFF_GATES, R_, 512, 128, 128, 0, 1);
    lstm_kernel<<<1024, 256>>>(c0, out);

    // output head
    sumhid_kernel<<<16, 128>>>(out);
    linear_kernel<<<dim3(4, 1), blk>>>(nullptr, OFF_SUMH, o_w0, o_b0, nullptr, OFF_O0, 16, 256, 128, 128, 1, 0);
    linear_kernel<<<dim3(1, 1), blk>>>(nullptr, OFF_O0,   o_w1, o_b1, out, 0,          16, 64,  256, 256, 1, 0);
}